// round 5
// baseline (speedup 1.0000x reference)
#include <cuda_runtime.h>
#include <cuda_bf16.h>

#define DIMC 256
#define HWD  56
#define NBLK 1568   // 32 images * 49 spatial blocks

// ---------------- device weight scratch (bf16) ----------------
__device__ __align__(16) __nv_bfloat16 g_W1B[256 * 1024]; // [K=256][N=1024]
__device__ __align__(16) __nv_bfloat16 g_W2B[1024 * 256]; // [K=1024][N=256]

__global__ void convert_weights(const float* __restrict__ w1,
                                const float* __restrict__ w2) {
    int id = blockIdx.x * blockDim.x + threadIdx.x;
    if (id < 256 * 1024) {
        g_W1B[id] = __float2bfloat16(w1[id]);
        g_W2B[id] = __float2bfloat16(w2[id]);
    }
}

// ---------------- smem layout (bytes) ----------------
// Y   : bf16 [64][264]                 ->  33792
// W1c : bf16 [256][136] (aliases: conv patch f32 8*14*40, zsm f32 64*261)
// W2c : bf16 [128][264] (aliases: dw weights f32 256*49)
// Hc  : bf16 [64][136]
#define Y_OFF    0
#define Y_STRIDE 264
#define W1C_OFF  33792
#define W1C_STRIDE 136
#define W2C_OFF  103424
#define W2C_STRIDE 264
#define HC_OFF   171008
#define HC_STRIDE 136
#define B1C_OFF  188416
#define DWB_OFF  188928
#define LNW_OFF  189952
#define LNB_OFF  190976
#define RS_OFF   192000
#define RQ_OFF   193024
#define SMEM_TOTAL 194048

__device__ __forceinline__ unsigned smem_u32(const void* p) {
    return (unsigned)__cvta_generic_to_shared(p);
}

__device__ __forceinline__ void ldsm4(unsigned r[4], unsigned addr) {
    asm volatile("ldmatrix.sync.aligned.m8n8.x4.shared.b16 {%0,%1,%2,%3}, [%4];"
                 : "=r"(r[0]), "=r"(r[1]), "=r"(r[2]), "=r"(r[3]) : "r"(addr));
}
__device__ __forceinline__ void ldsm4t(unsigned r[4], unsigned addr) {
    asm volatile("ldmatrix.sync.aligned.m8n8.x4.trans.shared.b16 {%0,%1,%2,%3}, [%4];"
                 : "=r"(r[0]), "=r"(r[1]), "=r"(r[2]), "=r"(r[3]) : "r"(addr));
}
__device__ __forceinline__ void mma16816(float d[4], const unsigned a[4],
                                         unsigned b0, unsigned b1) {
    asm volatile(
        "mma.sync.aligned.m16n8k16.row.col.f32.bf16.bf16.f32 "
        "{%0,%1,%2,%3}, {%4,%5,%6,%7}, {%8,%9}, {%0,%1,%2,%3};"
        : "+f"(d[0]), "+f"(d[1]), "+f"(d[2]), "+f"(d[3])
        : "r"(a[0]), "r"(a[1]), "r"(a[2]), "r"(a[3]), "r"(b0), "r"(b1));
}

__device__ __forceinline__ float gelu_f(float v) {
    // tanh approximation; error lands at 1e-9 of output after *gamma=1e-6
    float u = 0.7978845608028654f * (v + 0.044715f * v * v * v);
    float th;
    asm("tanh.approx.f32 %0, %1;" : "=f"(th) : "f"(u));
    return 0.5f * v * (1.0f + th);
}

__global__ __launch_bounds__(256, 1)
void block_kernel(const float* __restrict__ x, const int* __restrict__ mask,
                  const float* __restrict__ dw_w, const float* __restrict__ dw_b,
                  const float* __restrict__ ln_w, const float* __restrict__ ln_b,
                  const float* __restrict__ b1, const float* __restrict__ b2,
                  const float* __restrict__ gamma, float* __restrict__ out) {
    extern __shared__ char sm[];
    const int t   = threadIdx.x;
    const int blk = blockIdx.x;
    const int b   = blk / 49;
    const int s   = blk % 49;
    const int h0  = (s / 7) * 8;
    const int w0  = (s % 7) * 8;
    const float* xb = x   + (size_t)b * DIMC * HWD * HWD;
    float*       ob = out + (size_t)b * DIMC * HWD * HWD;

    if (mask[blk] == 0) {
        // inactive: out = x for this tile
        for (int i = t; i < 16384; i += 256) {
            int c = i >> 6, p = i & 63;
            int g = (c * HWD + h0 + (p >> 3)) * HWD + w0 + (p & 7);
            ob[g] = xb[g];
        }
        return;
    }

    __nv_bfloat16* Ys   = (__nv_bfloat16*)(sm + Y_OFF);
    float* patch = (float*)(sm + W1C_OFF);   // 8*14*40 f32, alias of W1c
    float* dws   = (float*)(sm + W2C_OFF);   // 256*49 f32, alias of W2c
    float* b1c   = (float*)(sm + B1C_OFF);
    float* dwb_s = (float*)(sm + DWB_OFF);
    float* lnw_s = (float*)(sm + LNW_OFF);
    float* lnb_s = (float*)(sm + LNB_OFF);
    float* rS    = (float*)(sm + RS_OFF);
    float* rQ    = (float*)(sm + RQ_OFF);

    // stage depthwise weights + per-channel consts
    for (int i = t; i < 256 * 49; i += 256) dws[i] = dw_w[i];
    dwb_s[t] = dw_b[t];
    lnw_s[t] = ln_w[t];
    lnb_s[t] = ln_b[t];

    // ---------------- depthwise conv 7x7 + stats ----------------
    const int ci = t >> 6;          // 0..3
    const int p  = t & 63;          // position in 8x8 tile
    const int pr = p >> 3, pc = p & 7;
    float sum = 0.f, ssq = 0.f;

    for (int st = 0; st < 32; st++) {
        const int c8 = st * 8;
        __syncthreads();
        // stage 8 channels of 14x14 padded patch
        for (int id = t; id < 8 * 196; id += 256) {
            int cc = id / 196, rem = id % 196;
            int rr = rem / 14, cw = rem % 14;
            int hh = h0 - 3 + rr, ww = w0 - 3 + cw;
            float v = 0.f;
            if ((unsigned)hh < 56u && (unsigned)ww < 56u)
                v = xb[((c8 + cc) * HWD + hh) * HWD + ww];
            patch[(cc * 14 + rr) * 40 + cw] = v;
        }
        __syncthreads();
        const int ca = c8 + ci, cb = c8 + ci + 4;
        float a0 = dwb_s[ca], a1 = dwb_s[cb];
        const float* wA = dws + ca * 49;
        const float* wB = dws + cb * 49;
        const float* pA = patch + (ci * 14 + pr) * 40 + pc;
        const float* pB = patch + ((ci + 4) * 14 + pr) * 40 + pc;
#pragma unroll
        for (int kh = 0; kh < 7; kh++) {
#pragma unroll
            for (int kw = 0; kw < 7; kw++) {
                a0 += pA[kh * 40 + kw] * wA[kh * 7 + kw];
                a1 += pB[kh * 40 + kw] * wB[kh * 7 + kw];
            }
        }
        sum += a0 + a1;
        ssq += a0 * a0 + a1 * a1;
        Ys[p * Y_STRIDE + ca] = __float2bfloat16(a0);
        Ys[p * Y_STRIDE + cb] = __float2bfloat16(a1);
    }

    rS[ci * 64 + p] = sum;
    rQ[ci * 64 + p] = ssq;
    __syncthreads();
    {
        float S = rS[p] + rS[64 + p] + rS[128 + p] + rS[192 + p];
        float Q = rQ[p] + rQ[64 + p] + rQ[128 + p] + rQ[192 + p];
        float mu   = S * (1.f / 256.f);
        float var  = Q * (1.f / 256.f) - mu * mu;
        float rstd = rsqrtf(fmaxf(var, 0.f) + 1e-6f);
        // LayerNorm apply (each thread owns exactly the channels it wrote)
        for (int st = 0; st < 32; st++) {
            int ca = st * 8 + ci, cb = ca + 4;
            float ya = __bfloat162float(Ys[p * Y_STRIDE + ca]);
            float yb = __bfloat162float(Ys[p * Y_STRIDE + cb]);
            ya = (ya - mu) * rstd * lnw_s[ca] + lnb_s[ca];
            yb = (yb - mu) * rstd * lnw_s[cb] + lnb_s[cb];
            Ys[p * Y_STRIDE + ca] = __float2bfloat16(ya);
            Ys[p * Y_STRIDE + cb] = __float2bfloat16(yb);
        }
    }

    // ---------------- MLP via mma.sync bf16 ----------------
    __nv_bfloat16* W1c = (__nv_bfloat16*)(sm + W1C_OFF);
    __nv_bfloat16* W2c = (__nv_bfloat16*)(sm + W2C_OFF);
    __nv_bfloat16* Hcn = (__nv_bfloat16*)(sm + HC_OFF);
    const int lane = t & 31, wrp = t >> 5;
    const int wm = wrp & 3, wn = wrp >> 2;   // 4 (M) x 2 (N) warp grid
    const int m0 = wm * 16;
    const unsigned Ybase  = smem_u32(Ys);
    const unsigned W1base = smem_u32(W1c);
    const unsigned W2base = smem_u32(W2c);
    const unsigned Hbase  = smem_u32(Hcn);
    const unsigned aOffY = Ybase + (m0 + (lane & 15)) * (Y_STRIDE * 2) + ((lane >> 4) << 4);
    const unsigned aOffH = Hbase + (m0 + (lane & 15)) * (HC_STRIDE * 2) + ((lane >> 4) << 4);

    float accZ[16][4];
#pragma unroll
    for (int i = 0; i < 16; i++)
#pragma unroll
        for (int j = 0; j < 4; j++) accZ[i][j] = 0.f;

    for (int nc = 0; nc < 8; nc++) {
        __syncthreads();  // prev GEMM2 done reading W2c/Hc
        // load W1 chunk [256 x 128] and W2 chunk [128 x 256] (bf16, uint4 vectors)
        {
            const uint4* s1 = (const uint4*)g_W1B;
            uint4*       d1 = (uint4*)W1c;
            for (int i = t; i < 4096; i += 256) {
                int k = i >> 4, j = i & 15;
                d1[k * 17 + j] = s1[k * 128 + nc * 16 + j];
            }
            const uint4* s2 = (const uint4*)g_W2B;
            uint4*       d2 = (uint4*)W2c;
            for (int i = t; i < 4096; i += 256) {
                int k = i >> 5, j = i & 31;
                d2[k * 33 + j] = s2[(nc * 128 + k) * 32 + j];
            }
            if (t < 128) b1c[t] = b1[nc * 128 + t];
        }
        __syncthreads();

        // GEMM1: H_chunk[64,128] = Y[64,256] @ W1c[256,128]
        float acc1[8][4];
#pragma unroll
        for (int i = 0; i < 8; i++)
#pragma unroll
            for (int j = 0; j < 4; j++) acc1[i][j] = 0.f;

#pragma unroll 4
        for (int kk = 0; kk < 256; kk += 16) {
            unsigned a[4];
            ldsm4(a, aOffY + kk * 2);
#pragma unroll
            for (int q = 0; q < 4; q++) {
                unsigned bq[4];
                ldsm4t(bq, W1base + (kk + (lane & 15)) * (W1C_STRIDE * 2)
                                 + (wn * 64 + q * 16) * 2 + ((lane >> 4) << 4));
                mma16816(acc1[2 * q],     a, bq[0], bq[1]);
                mma16816(acc1[2 * q + 1], a, bq[2], bq[3]);
            }
        }

        // bias + GELU + pack bf16 into Hc
#pragma unroll
        for (int q = 0; q < 8; q++) {
            int c0 = wn * 64 + q * 8 + 2 * (lane & 3);
            int r  = m0 + (lane >> 2);
            float f0 = gelu_f(acc1[q][0] + b1c[c0]);
            float f1 = gelu_f(acc1[q][1] + b1c[c0 + 1]);
            float f2 = gelu_f(acc1[q][2] + b1c[c0]);
            float f3 = gelu_f(acc1[q][3] + b1c[c0 + 1]);
            __nv_bfloat162 h01, h23;
            h01.x = __float2bfloat16(f0); h01.y = __float2bfloat16(f1);
            h23.x = __float2bfloat16(f2); h23.y = __float2bfloat16(f3);
            *(__nv_bfloat162*)&Hcn[r * HC_STRIDE + c0]       = h01;
            *(__nv_bfloat162*)&Hcn[(r + 8) * HC_STRIDE + c0] = h23;
        }
        __syncthreads();

        // GEMM2: Z[64,256] += H_chunk[64,128] @ W2c[128,256]
#pragma unroll 2
        for (int kk = 0; kk < 128; kk += 16) {
            unsigned a[4];
            ldsm4(a, aOffH + kk * 2);
#pragma unroll
            for (int q = 0; q < 8; q++) {
                unsigned bq[4];
                ldsm4t(bq, W2base + (kk + (lane & 15)) * (W2C_STRIDE * 2)
                                 + (wn * 128 + q * 16) * 2 + ((lane >> 4) << 4));
                mma16816(accZ[2 * q],     a, bq[0], bq[1]);
                mma16816(accZ[2 * q + 1], a, bq[2], bq[3]);
            }
        }
    }
    __syncthreads();

    // dump Z to smem (transpose buffer, stride 261 to dodge bank conflicts)
    float* zs = (float*)(sm + W1C_OFF);
#pragma unroll
    for (int q = 0; q < 16; q++) {
        int c0 = wn * 128 + q * 8 + 2 * (lane & 3);
        int r  = m0 + (lane >> 2);
        zs[r * 261 + c0]           = accZ[q][0];
        zs[r * 261 + c0 + 1]       = accZ[q][1];
        zs[(r + 8) * 261 + c0]     = accZ[q][2];
        zs[(r + 8) * 261 + c0 + 1] = accZ[q][3];
    }
    __syncthreads();

    // epilogue: out = x + (z + b2) * gamma  (mask==1 here)
    for (int i = t; i < 16384; i += 256) {
        int c = i >> 6, pp = i & 63;
        float z = (zs[pp * 261 + c] + b2[c]) * gamma[c];
        int g = (c * HWD + h0 + (pp >> 3)) * HWD + w0 + (pp & 7);
        ob[g] = xb[g] + z;
    }
}

extern "C" void kernel_launch(void* const* d_in, const int* in_sizes, int n_in,
                              void* d_out, int out_size) {
    const float* x     = (const float*)d_in[0];
    const int*   mask  = (const int*)d_in[1];
    const float* dw_w  = (const float*)d_in[2];
    const float* dw_b  = (const float*)d_in[3];
    const float* ln_w  = (const float*)d_in[4];
    const float* ln_b  = (const float*)d_in[5];
    const float* w1    = (const float*)d_in[6];
    const float* b1    = (const float*)d_in[7];
    const float* w2    = (const float*)d_in[8];
    const float* b2    = (const float*)d_in[9];
    const float* gamma = (const float*)d_in[10];
    float* out = (float*)d_out;

    convert_weights<<<512, 512>>>(w1, w2);

    cudaFuncSetAttribute(block_kernel,
                         cudaFuncAttributeMaxDynamicSharedMemorySize, SMEM_TOTAL);
    block_kernel<<<NBLK, 256, SMEM_TOTAL>>>(x, mask, dw_w, dw_b, ln_w, ln_b,
                                            b1, b2, gamma, out);
}

// round 8
// speedup vs baseline: 1.3360x; 1.3360x over previous
#include <cuda_runtime.h>
#include <cuda_bf16.h>

#define DIMC 256
#define HWD  56
#define NBLK 1568   // 32 images * 49 spatial blocks
#define NT   512    // threads per CTA (16 warps)

// ---------------- device weight scratch (bf16) ----------------
__device__ __align__(16) __nv_bfloat16 g_W1B[256 * 1024]; // [K=256][N=1024]
__device__ __align__(16) __nv_bfloat16 g_W2B[1024 * 256]; // [K=1024][N=256]

__global__ void convert_weights(const float* __restrict__ w1,
                                const float* __restrict__ w2) {
    int id = blockIdx.x * blockDim.x + threadIdx.x;
    if (id < 256 * 1024) {
        g_W1B[id] = __float2bfloat16(w1[id]);
        g_W2B[id] = __float2bfloat16(w2[id]);
    }
}

// ---------------- smem layout (bytes) ----------------
// Y   : bf16 [64][264]                 ->  33792
// W1c : bf16 [256][136] (aliases: conv patch f32 16*14*40, zsm f32 64*261)
// W2c : bf16 [128][264] (aliases: dw weights f32 256*49)
// Hc  : bf16 [64][136]
#define Y_OFF    0
#define Y_STRIDE 264
#define W1C_OFF  33792
#define W1C_STRIDE 136
#define W2C_OFF  103424
#define W2C_STRIDE 264
#define HC_OFF   171008
#define HC_STRIDE 136
#define B1C_OFF  188416
#define DWB_OFF  188928
#define LNW_OFF  189952
#define LNB_OFF  190976
#define RS_OFF   192000
#define RQ_OFF   194048
#define SMEM_TOTAL 196096

__device__ __forceinline__ unsigned smem_u32(const void* p) {
    return (unsigned)__cvta_generic_to_shared(p);
}

__device__ __forceinline__ void ldsm4(unsigned r[4], unsigned addr) {
    asm volatile("ldmatrix.sync.aligned.m8n8.x4.shared.b16 {%0,%1,%2,%3}, [%4];"
                 : "=r"(r[0]), "=r"(r[1]), "=r"(r[2]), "=r"(r[3]) : "r"(addr));
}
__device__ __forceinline__ void ldsm4t(unsigned r[4], unsigned addr) {
    asm volatile("ldmatrix.sync.aligned.m8n8.x4.trans.shared.b16 {%0,%1,%2,%3}, [%4];"
                 : "=r"(r[0]), "=r"(r[1]), "=r"(r[2]), "=r"(r[3]) : "r"(addr));
}
__device__ __forceinline__ void mma16816(float d[4], const unsigned a[4],
                                         unsigned b0, unsigned b1) {
    asm volatile(
        "mma.sync.aligned.m16n8k16.row.col.f32.bf16.bf16.f32 "
        "{%0,%1,%2,%3}, {%4,%5,%6,%7}, {%8,%9}, {%0,%1,%2,%3};"
        : "+f"(d[0]), "+f"(d[1]), "+f"(d[2]), "+f"(d[3])
        : "r"(a[0]), "r"(a[1]), "r"(a[2]), "r"(a[3]), "r"(b0), "r"(b1));
}

__device__ __forceinline__ float gelu_f(float v) {
    float u = 0.7978845608028654f * (v + 0.044715f * v * v * v);
    float th;
    asm("tanh.approx.f32 %0, %1;" : "=f"(th) : "f"(u));
    return 0.5f * v * (1.0f + th);
}

__global__ __launch_bounds__(NT, 1)
void block_kernel(const float* __restrict__ x, const int* __restrict__ mask,
                  const float* __restrict__ dw_w, const float* __restrict__ dw_b,
                  const float* __restrict__ ln_w, const float* __restrict__ ln_b,
                  const float* __restrict__ b1, const float* __restrict__ b2,
                  const float* __restrict__ gamma, float* __restrict__ out) {
    extern __shared__ char sm[];
    const int t   = threadIdx.x;
    const int blk = blockIdx.x;
    const int b   = blk / 49;
    const int s   = blk % 49;
    const int h0  = (s / 7) * 8;
    const int w0  = (s % 7) * 8;
    const float* xb = x   + (size_t)b * DIMC * HWD * HWD;
    float*       ob = out + (size_t)b * DIMC * HWD * HWD;

    if (mask[blk] == 0) {
        // inactive: out = x for this tile, float4-vectorized
        for (int i = t; i < 4096; i += NT) {
            int c = i >> 4, sub = i & 15;
            int rr = sub >> 1, half = sub & 1;
            size_t g = (size_t)(c * HWD + h0 + rr) * HWD + w0;
            const float4* src = (const float4*)(xb + g) + half;
            float4*       dst = (float4*)(ob + g) + half;
            *dst = *src;
        }
        return;
    }

    __nv_bfloat16* Ys   = (__nv_bfloat16*)(sm + Y_OFF);
    float* patch = (float*)(sm + W1C_OFF);   // 16*14*40 f32, alias of W1c
    float* dws   = (float*)(sm + W2C_OFF);   // 256*49 f32, alias of W2c
    float* b1c   = (float*)(sm + B1C_OFF);
    float* dwb_s = (float*)(sm + DWB_OFF);
    float* lnw_s = (float*)(sm + LNW_OFF);
    float* lnb_s = (float*)(sm + LNB_OFF);
    float* rS    = (float*)(sm + RS_OFF);
    float* rQ    = (float*)(sm + RQ_OFF);

    // stage depthwise weights + per-channel consts
    for (int i = t; i < 256 * 49; i += NT) dws[i] = dw_w[i];
    if (t < 256) {
        dwb_s[t] = dw_b[t];
        lnw_s[t] = ln_w[t];
        lnb_s[t] = ln_b[t];
    }

    // ---------------- depthwise conv 7x7 + stats ----------------
    const int ci = t >> 6;          // 0..7
    const int p  = t & 63;          // position in 8x8 tile
    const int pr = p >> 3, pc = p & 7;
    float sum = 0.f, ssq = 0.f;

    for (int st = 0; st < 16; st++) {
        const int c16 = st * 16;
        __syncthreads();
        // stage 16 channels of 14x14 padded patch
        for (int id = t; id < 16 * 196; id += NT) {
            int cc = id / 196, rem = id % 196;
            int rr = rem / 14, cw = rem % 14;
            int hh = h0 - 3 + rr, ww = w0 - 3 + cw;
            float v = 0.f;
            if ((unsigned)hh < 56u && (unsigned)ww < 56u)
                v = xb[((c16 + cc) * HWD + hh) * HWD + ww];
            patch[(cc * 14 + rr) * 40 + cw] = v;
        }
        __syncthreads();
        const int ca = c16 + ci, cb = c16 + ci + 8;
        float a0 = dwb_s[ca], a1 = dwb_s[cb];
        const float* wA = dws + ca * 49;
        const float* wB = dws + cb * 49;
        const float* pA = patch + (ci * 14 + pr) * 40 + pc;
        const float* pB = patch + ((ci + 8) * 14 + pr) * 40 + pc;
#pragma unroll
        for (int kh = 0; kh < 7; kh++) {
#pragma unroll
            for (int kw = 0; kw < 7; kw++) {
                a0 += pA[kh * 40 + kw] * wA[kh * 7 + kw];
                a1 += pB[kh * 40 + kw] * wB[kh * 7 + kw];
            }
        }
        sum += a0 + a1;
        ssq += a0 * a0 + a1 * a1;
        Ys[p * Y_STRIDE + ca] = __float2bfloat16(a0);
        Ys[p * Y_STRIDE + cb] = __float2bfloat16(a1);
    }

    rS[ci * 64 + p] = sum;
    rQ[ci * 64 + p] = ssq;
    __syncthreads();
    {
        float S = 0.f, Q = 0.f;
#pragma unroll
        for (int j = 0; j < 8; j++) { S += rS[j * 64 + p]; Q += rQ[j * 64 + p]; }
        float mu   = S * (1.f / 256.f);
        float var  = Q * (1.f / 256.f) - mu * mu;
        float rstd = rsqrtf(fmaxf(var, 0.f) + 1e-6f);
        // LayerNorm apply (each thread owns exactly the channels it wrote)
        for (int st = 0; st < 16; st++) {
            int ca = st * 16 + ci, cb = ca + 8;
            float ya = __bfloat162float(Ys[p * Y_STRIDE + ca]);
            float yb = __bfloat162float(Ys[p * Y_STRIDE + cb]);
            ya = (ya - mu) * rstd * lnw_s[ca] + lnb_s[ca];
            yb = (yb - mu) * rstd * lnw_s[cb] + lnb_s[cb];
            Ys[p * Y_STRIDE + ca] = __float2bfloat16(ya);
            Ys[p * Y_STRIDE + cb] = __float2bfloat16(yb);
        }
    }

    // ---------------- MLP via mma.sync bf16 (16 warps: 4M x 4N) ----------------
    __nv_bfloat16* W1c = (__nv_bfloat16*)(sm + W1C_OFF);
    __nv_bfloat16* W2c = (__nv_bfloat16*)(sm + W2C_OFF);
    __nv_bfloat16* Hcn = (__nv_bfloat16*)(sm + HC_OFF);
    const int lane = t & 31, wrp = t >> 5;
    const int wm = wrp & 3, wn = wrp >> 2;   // 4 (M) x 4 (N) warp grid
    const int m0 = wm * 16;
    const unsigned Ybase  = smem_u32(Ys);
    const unsigned W1base = smem_u32(W1c);
    const unsigned W2base = smem_u32(W2c);
    const unsigned Hbase  = smem_u32(Hcn);
    const unsigned aOffY = Ybase + (m0 + (lane & 15)) * (Y_STRIDE * 2) + ((lane >> 4) << 4);
    const unsigned aOffH = Hbase + (m0 + (lane & 15)) * (HC_STRIDE * 2) + ((lane >> 4) << 4);

    float accZ[8][4];
#pragma unroll
    for (int i = 0; i < 8; i++)
#pragma unroll
        for (int j = 0; j < 4; j++) accZ[i][j] = 0.f;

    for (int nc = 0; nc < 8; nc++) {
        __syncthreads();  // prev GEMM2 done reading W2c/Hc
        // load W1 chunk [256 x 128] and W2 chunk [128 x 256] (bf16, uint4 vectors)
        {
            const uint4* s1 = (const uint4*)g_W1B;
            uint4*       d1 = (uint4*)W1c;
            for (int i = t; i < 4096; i += NT) {
                int k = i >> 4, j = i & 15;
                d1[k * 17 + j] = s1[k * 128 + nc * 16 + j];
            }
            const uint4* s2 = (const uint4*)g_W2B;
            uint4*       d2 = (uint4*)W2c;
            for (int i = t; i < 4096; i += NT) {
                int k = i >> 5, j = i & 31;
                d2[k * 33 + j] = s2[(nc * 128 + k) * 32 + j];
            }
            if (t < 128) b1c[t] = b1[nc * 128 + t];
        }
        __syncthreads();

        // GEMM1: H_chunk[64,128] = Y[64,256] @ W1c[256,128]; warp tile 16x32
        float acc1[4][4];
#pragma unroll
        for (int i = 0; i < 4; i++)
#pragma unroll
            for (int j = 0; j < 4; j++) acc1[i][j] = 0.f;

#pragma unroll 4
        for (int kk = 0; kk < 256; kk += 16) {
            unsigned a[4];
            ldsm4(a, aOffY + kk * 2);
#pragma unroll
            for (int q = 0; q < 2; q++) {
                unsigned bq[4];
                ldsm4t(bq, W1base + (kk + (lane & 15)) * (W1C_STRIDE * 2)
                                 + (wn * 32 + q * 16) * 2 + ((lane >> 4) << 4));
                mma16816(acc1[2 * q],     a, bq[0], bq[1]);
                mma16816(acc1[2 * q + 1], a, bq[2], bq[3]);
            }
        }

        // bias + GELU + pack bf16 into Hc
#pragma unroll
        for (int q = 0; q < 4; q++) {
            int c0 = wn * 32 + q * 8 + 2 * (lane & 3);
            int r  = m0 + (lane >> 2);
            float f0 = gelu_f(acc1[q][0] + b1c[c0]);
            float f1 = gelu_f(acc1[q][1] + b1c[c0 + 1]);
            float f2 = gelu_f(acc1[q][2] + b1c[c0]);
            float f3 = gelu_f(acc1[q][3] + b1c[c0 + 1]);
            __nv_bfloat162 h01, h23;
            h01.x = __float2bfloat16(f0); h01.y = __float2bfloat16(f1);
            h23.x = __float2bfloat16(f2); h23.y = __float2bfloat16(f3);
            *(__nv_bfloat162*)&Hcn[r * HC_STRIDE + c0]       = h01;
            *(__nv_bfloat162*)&Hcn[(r + 8) * HC_STRIDE + c0] = h23;
        }
        __syncthreads();

        // GEMM2: Z[64,256] += H_chunk[64,128] @ W2c[128,256]; warp tile 16x64
#pragma unroll 2
        for (int kk = 0; kk < 128; kk += 16) {
            unsigned a[4];
            ldsm4(a, aOffH + kk * 2);
#pragma unroll
            for (int q = 0; q < 4; q++) {
                unsigned bq[4];
                ldsm4t(bq, W2base + (kk + (lane & 15)) * (W2C_STRIDE * 2)
                                 + (wn * 64 + q * 16) * 2 + ((lane >> 4) << 4));
                mma16816(accZ[2 * q],     a, bq[0], bq[1]);
                mma16816(accZ[2 * q + 1], a, bq[2], bq[3]);
            }
        }
    }
    __syncthreads();

    // dump Z to smem (transpose buffer, stride 261 to dodge bank conflicts)
    float* zs = (float*)(sm + W1C_OFF);
#pragma unroll
    for (int q = 0; q < 8; q++) {
        int c0 = wn * 64 + q * 8 + 2 * (lane & 3);
        int r  = m0 + (lane >> 2);
        zs[r * 261 + c0]           = accZ[q][0];
        zs[r * 261 + c0 + 1]       = accZ[q][1];
        zs[(r + 8) * 261 + c0]     = accZ[q][2];
        zs[(r + 8) * 261 + c0 + 1] = accZ[q][3];
    }
    __syncthreads();

    // epilogue: out = x + (z + b2) * gamma, float4-vectorized (mask==1 here)
    for (int i = t; i < 4096; i += NT) {
        int c = i >> 4, sub = i & 15;
        int rr = sub >> 1, half = sub & 1;
        int pp = rr * 8 + half * 4;
        float gm = __ldg(gamma + c), bb = __ldg(b2 + c);
        float4 z4;
        z4.x = (zs[(pp + 0) * 261 + c] + bb) * gm;
        z4.y = (zs[(pp + 1) * 261 + c] + bb) * gm;
        z4.z = (zs[(pp + 2) * 261 + c] + bb) * gm;
        z4.w = (zs[(pp + 3) * 261 + c] + bb) * gm;
        size_t g = (size_t)(c * HWD + h0 + rr) * HWD + w0;
        const float4* src = (const float4*)(xb + g) + half;
        float4*       dst = (float4*)(ob + g) + half;
        float4 xv = *src;
        xv.x += z4.x; xv.y += z4.y; xv.z += z4.z; xv.w += z4.w;
        *dst = xv;
    }
}

extern "C" void kernel_launch(void* const* d_in, const int* in_sizes, int n_in,
                              void* d_out, int out_size) {
    const float* x     = (const float*)d_in[0];
    const int*   mask  = (const int*)d_in[1];
    const float* dw_w  = (const float*)d_in[2];
    const float* dw_b  = (const float*)d_in[3];
    const float* ln_w  = (const float*)d_in[4];
    const float* ln_b  = (const float*)d_in[5];
    const float* w1    = (const float*)d_in[6];
    const float* b1    = (const float*)d_in[7];
    const float* w2    = (const float*)d_in[8];
    const float* b2    = (const float*)d_in[9];
    const float* gamma = (const float*)d_in[10];
    float* out = (float*)d_out;

    convert_weights<<<512, 512>>>(w1, w2);

    cudaFuncSetAttribute(block_kernel,
                         cudaFuncAttributeMaxDynamicSharedMemorySize, SMEM_TOTAL);
    block_kernel<<<NBLK, NT, SMEM_TOTAL>>>(x, mask, dw_w, dw_b, ln_w, ln_b,
                                           b1, b2, gamma, out);
}